// round 1
// baseline (speedup 1.0000x reference)
#include <cuda_runtime.h>
#include <cuda_bf16.h>
#include <math.h>

// ---------------- static problem sizes ----------------
#define NB     32          // batches (graphs)
#define SEQ    1024        // nodes per graph
#define NTOT   (NB*SEQ)    // 32768
#define DIM    128
#define NHEAD  4
#define HDIM   32
#define NLAY   3
#define DFF    2048
#define INDIM  64

// ---------------- scratch (device globals; no allocs allowed) ----------------
__device__ float g_h   [NTOT * DIM];    // current hidden state
__device__ float g_qkv [NTOT * 3*DIM];  // qkv projections
__device__ float g_attn[NTOT * DIM];    // attention output
__device__ float g_tmp [NTOT * DIM];    // gemm epilogue buffer (pre-LN delta)
__device__ float g_ffn [NTOT * DFF];    // ffn hidden
__device__ float g_mask[NTOT];          // node mask (from post-projection h)

__device__ __forceinline__ float* sel_buf(int id, const float* ext) {
    switch (id) {
        case 0: return g_h;
        case 1: return g_qkv;
        case 2: return g_attn;
        case 3: return g_tmp;
        case 4: return g_ffn;
        default: return (float*)ext;
    }
}

// ---------------- SGEMM: C[M,Nc] = A[M,K] @ W[Nc,K]^T + bias (opt. ReLU) ----
// 128x128 block tile, 8x8 thread tile, BK=8, 256 threads.
// All shapes here are multiples of the tiles (M=32768; Nc in {128,384,2048};
// K in {64,128,2048}) so no bounds checks.
template<bool RELU>
__global__ void __launch_bounds__(256) sgemm_k(
    int aid, const float* __restrict__ aext,
    const float* __restrict__ W, const float* __restrict__ bias,
    int cid, int M, int Ncols, int K)
{
    const float* A = sel_buf(aid, aext);
    float*       C = sel_buf(cid, nullptr);

    const int bm = blockIdx.y * 128;
    const int bn = blockIdx.x * 128;

    __shared__ float As[8][132];   // padded: conflict-free stores & aligned ld.128
    __shared__ float Bs[8][132];

    const int tid = threadIdx.x;
    const int lr  = tid >> 1;          // 0..127  row within tile
    const int lc  = (tid & 1) * 4;     // 0 or 4  k-offset

    const float* Aload = A + (size_t)(bm + lr) * K + lc;
    const float* Wload = W + (size_t)(bn + lr) * K + lc;

    const int tx = tid & 15;           // output col group
    const int ty = tid >> 4;           // output row group

    float acc[8][8];
    #pragma unroll
    for (int i = 0; i < 8; i++)
        #pragma unroll
        for (int j = 0; j < 8; j++) acc[i][j] = 0.f;

    for (int k0 = 0; k0 < K; k0 += 8) {
        float4 a4 = *(const float4*)(Aload + k0);
        float4 b4 = *(const float4*)(Wload + k0);
        As[lc+0][lr] = a4.x; As[lc+1][lr] = a4.y;
        As[lc+2][lr] = a4.z; As[lc+3][lr] = a4.w;
        Bs[lc+0][lr] = b4.x; Bs[lc+1][lr] = b4.y;
        Bs[lc+2][lr] = b4.z; Bs[lc+3][lr] = b4.w;
        __syncthreads();

        #pragma unroll
        for (int k = 0; k < 8; k++) {
            float ra[8], rb[8];
            #pragma unroll
            for (int i = 0; i < 8; i++) ra[i] = As[k][ty*8 + i];
            #pragma unroll
            for (int j = 0; j < 8; j++) rb[j] = Bs[k][tx*8 + j];
            #pragma unroll
            for (int i = 0; i < 8; i++)
                #pragma unroll
                for (int j = 0; j < 8; j++)
                    acc[i][j] = fmaf(ra[i], rb[j], acc[i][j]);
        }
        __syncthreads();
    }

    // epilogue
    float rbias[8];
    #pragma unroll
    for (int j = 0; j < 8; j++) rbias[j] = bias[bn + tx*8 + j];

    #pragma unroll
    for (int i = 0; i < 8; i++) {
        const int row = bm + ty*8 + i;
        float v[8];
        #pragma unroll
        for (int j = 0; j < 8; j++) {
            float t = acc[i][j] + rbias[j];
            if (RELU) t = fmaxf(t, 0.f);
            v[j] = t;
        }
        float* cp = C + (size_t)row * Ncols + bn + tx*8;
        *(float4*)(cp    ) = make_float4(v[0], v[1], v[2], v[3]);
        *(float4*)(cp + 4) = make_float4(v[4], v[5], v[6], v[7]);
    }
}

// ---------------- flash attention ----------------
// grid = B*H*(SEQ/64) blocks, 64 threads. Each thread owns one q row:
// q[32], o[32] in registers; K/V tiles transposed in smem ([d][k], pad 65
// -> conflict-free stores, broadcast reads).
__global__ void __launch_bounds__(64) attn_k()
{
    const int blk = blockIdx.x;
    const int qt  = blk & 15;          // q tile (16 per b,h)
    const int bh  = blk >> 4;
    const int b   = bh >> 2;
    const int h   = bh & 3;
    const int t   = threadIdx.x;
    const int qrow = qt * 64 + t;

    const float scale = 0.1767766952966369f;   // 1/sqrt(32)
    const float* base = g_qkv + (size_t)(b * SEQ) * (3*DIM) + h * HDIM;

    float q[HDIM];
    {
        const float4* qp = (const float4*)(base + (size_t)qrow * (3*DIM));
        #pragma unroll
        for (int i = 0; i < 8; i++) {
            float4 v = qp[i];
            q[4*i+0] = v.x * scale; q[4*i+1] = v.y * scale;
            q[4*i+2] = v.z * scale; q[4*i+3] = v.w * scale;
        }
    }

    float o[HDIM];
    #pragma unroll
    for (int d = 0; d < HDIM; d++) o[d] = 0.f;
    float m = -1e30f, l = 0.f;

    __shared__ float Ks[HDIM][65];
    __shared__ float Vs[HDIM][65];

    for (int kt = 0; kt < SEQ/64; kt++) {
        __syncthreads();
        {
            const float* kp = base + DIM   + (size_t)(kt*64 + t) * (3*DIM);
            const float* vp = base + 2*DIM + (size_t)(kt*64 + t) * (3*DIM);
            float4 kk[8], vv[8];
            #pragma unroll
            for (int i = 0; i < 8; i++) {
                kk[i] = ((const float4*)kp)[i];
                vv[i] = ((const float4*)vp)[i];
            }
            #pragma unroll
            for (int i = 0; i < 8; i++) {
                Ks[4*i+0][t] = kk[i].x; Ks[4*i+1][t] = kk[i].y;
                Ks[4*i+2][t] = kk[i].z; Ks[4*i+3][t] = kk[i].w;
                Vs[4*i+0][t] = vv[i].x; Vs[4*i+1][t] = vv[i].y;
                Vs[4*i+2][t] = vv[i].z; Vs[4*i+3][t] = vv[i].w;
            }
        }
        __syncthreads();

        #pragma unroll 4
        for (int k = 0; k < 64; k++) {
            float s = 0.f;
            #pragma unroll
            for (int d = 0; d < HDIM; d++) s = fmaf(q[d], Ks[d][k], s);
            const float nm   = fmaxf(m, s);
            const float p    = __expf(s - nm);
            const float corr = __expf(m - nm);
            l = l * corr + p;
            #pragma unroll
            for (int d = 0; d < HDIM; d++)
                o[d] = fmaf(o[d], corr, p * Vs[d][k]);
            m = nm;
        }
    }

    const float inv = 1.f / l;
    float* op = g_attn + (size_t)(b * SEQ + qrow) * DIM + h * HDIM;
    #pragma unroll
    for (int i = 0; i < 8; i++)
        ((float4*)op)[i] = make_float4(o[4*i+0]*inv, o[4*i+1]*inv,
                                       o[4*i+2]*inv, o[4*i+3]*inv);
}

// ---------------- residual add + LayerNorm (in place into g_h) -------------
// g_h[row] = LN(g_h[row] + g_tmp[row]) * gamma + beta.  One warp per row.
__global__ void __launch_bounds__(256) add_ln_k(
    const float* __restrict__ gamma, const float* __restrict__ beta)
{
    const int warp = threadIdx.x >> 5;
    const int lane = threadIdx.x & 31;
    const int row  = blockIdx.x * 8 + warp;

    const float* r  = g_h   + (size_t)row * DIM;
    const float* dl = g_tmp + (size_t)row * DIM;

    float v[4];
    #pragma unroll
    for (int i = 0; i < 4; i++) v[i] = r[lane + 32*i] + dl[lane + 32*i];

    float s = v[0] + v[1] + v[2] + v[3];
    #pragma unroll
    for (int off = 16; off; off >>= 1) s += __shfl_xor_sync(~0u, s, off);
    const float mean = s * (1.f / DIM);

    float var = 0.f;
    #pragma unroll
    for (int i = 0; i < 4; i++) { float d = v[i] - mean; var = fmaf(d, d, var); }
    #pragma unroll
    for (int off = 16; off; off >>= 1) var += __shfl_xor_sync(~0u, var, off);
    const float inv = rsqrtf(var * (1.f / DIM) + 1e-5f);

    float* w = g_h + (size_t)row * DIM;
    #pragma unroll
    for (int i = 0; i < 4; i++) {
        const int c = lane + 32*i;
        w[c] = (v[i] - mean) * inv * gamma[c] + beta[c];
    }
}

// ---------------- node mask from post-projection h --------------------------
__global__ void __launch_bounds__(256) mask_k()
{
    const int warp = threadIdx.x >> 5;
    const int lane = threadIdx.x & 31;
    const int row  = blockIdx.x * 8 + warp;
    const float* r = g_h + (size_t)row * DIM;
    float s = 0.f;
    #pragma unroll
    for (int i = 0; i < 4; i++) s += r[lane + 32*i];
    #pragma unroll
    for (int off = 16; off; off >>= 1) s += __shfl_xor_sync(~0u, s, off);
    if (lane == 0) g_mask[row] = (s != 0.f) ? 1.f : 0.f;
}

// ---------------- masked mean pooling --------------------------------------
__global__ void __launch_bounds__(DIM) pool_k(float* __restrict__ out)
{
    const int b = blockIdx.x;
    const int d = threadIdx.x;
    float acc = 0.f, ms = 0.f;
    for (int s = 0; s < SEQ; s++) {
        const float mk = g_mask[b * SEQ + s];
        acc = fmaf(g_h[(size_t)(b * SEQ + s) * DIM + d], mk, acc);
        ms += mk;
    }
    out[b * DIM + d] = acc / ms;
}

// ---------------- driver -----------------------------------------------------
extern "C" void kernel_launch(void* const* d_in, const int* in_sizes, int n_in,
                              void* d_out, int out_size)
{
    const float* x     = (const float*)d_in[0];   // [N, 64]
    // d_in[1] = batch (int32) -- layout is static repeat(arange(B), N_PER); unused
    const float* W_in  = (const float*)d_in[2];   // [128, 64]
    const float* b_in  = (const float*)d_in[3];   // [128]
    const float* Wqkv  = (const float*)d_in[4];   // [L, 384, 128]
    const float* bqkv  = (const float*)d_in[5];   // [L, 384]
    const float* Wo    = (const float*)d_in[6];   // [L, 128, 128]
    const float* bo    = (const float*)d_in[7];   // [L, 128]
    const float* W1    = (const float*)d_in[8];   // [L, 2048, 128]
    const float* b1    = (const float*)d_in[9];   // [L, 2048]
    const float* W2    = (const float*)d_in[10];  // [L, 128, 2048]
    const float* b2    = (const float*)d_in[11];  // [L, 128]
    const float* ln1g  = (const float*)d_in[12];  // [L, 128]
    const float* ln1b  = (const float*)d_in[13];
    const float* ln2g  = (const float*)d_in[14];
    const float* ln2b  = (const float*)d_in[15];
    float* out = (float*)d_out;

    const int MROW = NTOT / 128;   // 256 row-tiles

    // input projection: g_h = x @ W_in^T + b_in
    sgemm_k<false><<<dim3(DIM/128, MROW), 256>>>(5, x, W_in, b_in, 0, NTOT, DIM, INDIM);
    // node mask from projected inputs
    mask_k<<<NTOT/8, 256>>>();

    for (int l = 0; l < NLAY; l++) {
        // qkv = h @ Wqkv^T + bqkv
        sgemm_k<false><<<dim3(3*DIM/128, MROW), 256>>>(
            0, nullptr, Wqkv + (size_t)l*3*DIM*DIM, bqkv + l*3*DIM, 1, NTOT, 3*DIM, DIM);
        // flash attention -> g_attn
        attn_k<<<NB*NHEAD*(SEQ/64), 64>>>();
        // o-proj -> g_tmp
        sgemm_k<false><<<dim3(DIM/128, MROW), 256>>>(
            2, nullptr, Wo + (size_t)l*DIM*DIM, bo + l*DIM, 3, NTOT, DIM, DIM);
        // h = LN(h + g_tmp)
        add_ln_k<<<NTOT/8, 256>>>(ln1g + l*DIM, ln1b + l*DIM);
        // ffn1 = relu(h @ W1^T + b1)
        sgemm_k<true><<<dim3(DFF/128, MROW), 256>>>(
            0, nullptr, W1 + (size_t)l*DFF*DIM, b1 + l*DFF, 4, NTOT, DFF, DIM);
        // ffn2 -> g_tmp
        sgemm_k<false><<<dim3(DIM/128, MROW), 256>>>(
            4, nullptr, W2 + (size_t)l*DIM*DFF, b2 + l*DIM, 3, NTOT, DIM, DFF);
        // h = LN(h + g_tmp)
        add_ln_k<<<NTOT/8, 256>>>(ln2g + l*DIM, ln2b + l*DIM);
    }

    pool_k<<<NB, DIM>>>(out);
}

// round 4
// speedup vs baseline: 1.2287x; 1.2287x over previous
#include <cuda_runtime.h>
#include <cuda_bf16.h>
#include <math.h>
#include <cstdint>

// ---------------- static problem sizes ----------------
#define NB     32
#define SEQ    1024
#define NTOT   (NB*SEQ)     // 32768
#define DIM    128
#define NHEAD  4
#define HDIM   32
#define NLAY   3
#define DFF    2048
#define INDIM  64

#define SMPAD  36           // floats per smem row (conflict-free frag gathers)
#define TILEB  (128*SMPAD)  // floats per tile buffer
#define SMEM_DYN (4*TILEB*4) // bytes: A0,B0,A1,B1

// ---------------- scratch (device globals; no allocs allowed) ---------------
__device__ float g_h   [NTOT * DIM];
__device__ float g_qkv [NTOT * 3*DIM];
__device__ float g_attn[NTOT * DIM];
__device__ float g_tmp [NTOT * DIM];
__device__ float g_ffn [NTOT * DFF];
__device__ float g_mask[NTOT];

__device__ __forceinline__ float* sel_buf(int id, const float* ext) {
    switch (id) {
        case 0: return g_h;
        case 1: return g_qkv;
        case 2: return g_attn;
        case 3: return g_tmp;
        case 4: return g_ffn;
        default: return (float*)ext;
    }
}

// ---------------- small PTX helpers ----------------
__device__ __forceinline__ uint32_t cvta_smem(const void* p) {
    uint32_t a;
    asm("{ .reg .u64 t; cvta.to.shared.u64 t, %1; cvt.u32.u64 %0, t; }"
        : "=r"(a) : "l"(p));
    return a;
}
__device__ __forceinline__ void cp16(uint32_t saddr, const void* gaddr) {
    asm volatile("cp.async.cg.shared.global [%0], [%1], 16;"
                 :: "r"(saddr), "l"(gaddr));
}
#define CP_COMMIT() asm volatile("cp.async.commit_group;" ::: "memory")
#define CP_WAIT0()  asm volatile("cp.async.wait_group 0;" ::: "memory")
#define CP_WAIT1()  asm volatile("cp.async.wait_group 1;" ::: "memory")

// split fp32 -> (tf32_hi rounded-to-nearest, tf32(residual))
__device__ __forceinline__ void tf32_split(float x, uint32_t& hi, uint32_t& lo) {
    asm("cvt.rna.tf32.f32 %0, %1;" : "=r"(hi) : "f"(x));
    float r = x - __uint_as_float(hi);
    asm("cvt.rna.tf32.f32 %0, %1;" : "=r"(lo) : "f"(r));
}

__device__ __forceinline__ void mma8(float* d, uint32_t a0, uint32_t a1,
                                     uint32_t a2, uint32_t a3,
                                     uint32_t b0, uint32_t b1) {
    asm volatile(
        "mma.sync.aligned.m16n8k8.row.col.f32.tf32.tf32.f32 "
        "{%0,%1,%2,%3}, {%4,%5,%6,%7}, {%8,%9}, {%0,%1,%2,%3};"
        : "+f"(d[0]), "+f"(d[1]), "+f"(d[2]), "+f"(d[3])
        : "r"(a0), "r"(a1), "r"(a2), "r"(a3), "r"(b0), "r"(b1));
}

// ---------------- 3xTF32 mma GEMM: C[M,Nc] = A[M,K] @ W[Nc,K]^T + bias -----
// 128x128 block tile, 256 threads, warp grid 4(m)x2(n), warp tile 32x64.
// K-chunks of 32 floats, cp.async double-buffered. Each fp32 operand split
// into tf32 hi+lo; acc += hi*hi + lo*hi + hi*lo (fp32-accurate).
template<bool RELU>
__global__ void __launch_bounds__(256) gemm_mma_k(
    int aid, const float* __restrict__ aext,
    const float* __restrict__ W, const float* __restrict__ bias,
    int cid, int Ncols, int K)
{
    extern __shared__ float sm[];
    float* bufA[2] = { sm,            sm + 2*TILEB };
    float* bufB[2] = { sm + TILEB,    sm + 3*TILEB };

    const float* A = sel_buf(aid, aext);
    float*       C = sel_buf(cid, nullptr);

    const int bm = blockIdx.y * 128;
    const int bn = blockIdx.x * 128;

    const int tid  = threadIdx.x;
    const int lane = tid & 31;
    const int warp = tid >> 5;
    const int wm   = warp & 3;      // 0..3  (m)
    const int wn   = warp >> 2;     // 0..1  (n)
    const int g    = lane >> 2;     // groupID 0..7
    const int cth  = lane & 3;      // threadID_in_group 0..3

    const int lrow = tid >> 3;
    const int lc4  = tid & 7;
    const float* Abase = A + (size_t)(bm + lrow) * K + lc4 * 4;
    const float* Wbase = W + (size_t)(bn + lrow) * K + lc4 * 4;
    const uint32_t sA[2] = { cvta_smem(bufA[0]), cvta_smem(bufA[1]) };
    const uint32_t sB[2] = { cvta_smem(bufB[0]), cvta_smem(bufB[1]) };
    const uint32_t soff  = (uint32_t)((lrow * SMPAD + lc4 * 4) * 4);

    float acc[2][8][4];
    #pragma unroll
    for (int mf = 0; mf < 2; mf++)
        #pragma unroll
        for (int nf = 0; nf < 8; nf++)
            #pragma unroll
            for (int j = 0; j < 4; j++) acc[mf][nf][j] = 0.f;

    const int nch = K >> 5;

    // prologue: chunk 0 -> buffer 0
    #pragma unroll
    for (int i = 0; i < 4; i++) {
        const uint32_t so = soff + (uint32_t)(i * 32 * SMPAD * 4);
        cp16(sA[0] + so, Abase + (size_t)i * 32 * K);
        cp16(sB[0] + so, Wbase + (size_t)i * 32 * K);
    }
    CP_COMMIT();

    for (int ch = 0; ch < nch; ch++) {
        const int cur = ch & 1;
        if (ch + 1 < nch) {
            const int nxt = cur ^ 1;
            const int k0 = (ch + 1) << 5;
            #pragma unroll
            for (int i = 0; i < 4; i++) {
                const uint32_t so = soff + (uint32_t)(i * 32 * SMPAD * 4);
                cp16(sA[nxt] + so, Abase + (size_t)i * 32 * K + k0);
                cp16(sB[nxt] + so, Wbase + (size_t)i * 32 * K + k0);
            }
            CP_COMMIT();
            CP_WAIT1();
        } else {
            CP_WAIT0();
        }
        __syncthreads();

        const float* As = bufA[cur];
        const float* Bs = bufB[cur];

        #pragma unroll
        for (int ks = 0; ks < 4; ks++) {
            const int kb = ks * 8 + cth;

            uint32_t ah[2][4], al[2][4];
            #pragma unroll
            for (int mf = 0; mf < 2; mf++) {
                const float* ar = As + (wm*32 + mf*16 + g) * SMPAD;
                tf32_split(ar[kb],             ah[mf][0], al[mf][0]);
                tf32_split(ar[8*SMPAD + kb],   ah[mf][1], al[mf][1]);
                tf32_split(ar[kb + 4],         ah[mf][2], al[mf][2]);
                tf32_split(ar[8*SMPAD + kb+4], ah[mf][3], al[mf][3]);
            }
            #pragma unroll
            for (int nf = 0; nf < 8; nf++) {
                const float* br = Bs + (wn*64 + nf*8 + g) * SMPAD;
                uint32_t bh0, bl0, bh1, bl1;
                tf32_split(br[kb],     bh0, bl0);
                tf32_split(br[kb + 4], bh1, bl1);
                #pragma unroll
                for (int mf = 0; mf < 2; mf++) {
                    float* d = acc[mf][nf];
                    mma8(d, ah[mf][0], ah[mf][1], ah[mf][2], ah[mf][3], bh0, bh1);
                    mma8(d, al[mf][0], al[mf][1], al[mf][2], al[mf][3], bh0, bh1);
                    mma8(d, ah[mf][0], ah[mf][1], ah[mf][2], ah[mf][3], bl0, bl1);
                }
            }
        }
        __syncthreads();
    }

    // epilogue: bias (+ReLU), direct global store
    #pragma unroll
    for (int nf = 0; nf < 8; nf++) {
        const int col = bn + wn*64 + nf*8 + cth*2;
        const float bx = __ldg(bias + col);
        const float by = __ldg(bias + col + 1);
        #pragma unroll
        for (int mf = 0; mf < 2; mf++) {
            const int row = bm + wm*32 + mf*16 + g;
            float2 v0 = make_float2(acc[mf][nf][0] + bx, acc[mf][nf][1] + by);
            float2 v1 = make_float2(acc[mf][nf][2] + bx, acc[mf][nf][3] + by);
            if (RELU) {
                v0.x = fmaxf(v0.x, 0.f); v0.y = fmaxf(v0.y, 0.f);
                v1.x = fmaxf(v1.x, 0.f); v1.y = fmaxf(v1.y, 0.f);
            }
            *(float2*)(C + (size_t)row * Ncols + col)       = v0;
            *(float2*)(C + (size_t)(row + 8) * Ncols + col) = v1;
        }
    }
}

// ---------------- flash attention (tile-wise softmax rescale) ---------------
__global__ void __launch_bounds__(128) attn_k()
{
    const int blk = blockIdx.x;
    const int qt  = blk & 7;
    const int bh  = blk >> 3;
    const int b   = bh >> 2;
    const int h   = bh & 3;
    const int t   = threadIdx.x;
    const int qrow = qt * 128 + t;

    const float scale = 0.1767766952966369f;   // 1/sqrt(32)
    const float* base = g_qkv + (size_t)(b * SEQ) * (3*DIM) + h * HDIM;

    float q[HDIM];
    {
        const float4* qp = (const float4*)(base + (size_t)qrow * (3*DIM));
        #pragma unroll
        for (int i = 0; i < 8; i++) {
            float4 v = qp[i];
            q[4*i+0] = v.x * scale; q[4*i+1] = v.y * scale;
            q[4*i+2] = v.z * scale; q[4*i+3] = v.w * scale;
        }
    }

    float o[HDIM];
    #pragma unroll
    for (int d = 0; d < HDIM; d++) o[d] = 0.f;
    float m = -1e30f, l = 0.f;

    __shared__ float Ks[HDIM][65];
    __shared__ float Vs[HDIM][65];

    for (int kt = 0; kt < SEQ/64; kt++) {
        __syncthreads();
        {
            const int kr = t & 63;
            const float* p = base + ((t < 64) ? DIM : 2*DIM)
                           + (size_t)(kt*64 + kr) * (3*DIM);
            float4 rr[8];
            #pragma unroll
            for (int i = 0; i < 8; i++) rr[i] = ((const float4*)p)[i];
            float (*dst)[65] = (t < 64) ? Ks : Vs;
            #pragma unroll
            for (int i = 0; i < 8; i++) {
                dst[4*i+0][kr] = rr[i].x; dst[4*i+1][kr] = rr[i].y;
                dst[4*i+2][kr] = rr[i].z; dst[4*i+3][kr] = rr[i].w;
            }
        }
        __syncthreads();

        #pragma unroll
        for (int half = 0; half < 2; half++) {
            const int kb = half * 32;
            float s[32];
            #pragma unroll
            for (int k = 0; k < 32; k++) {
                float acc = 0.f;
                #pragma unroll
                for (int d = 0; d < HDIM; d++)
                    acc = fmaf(q[d], Ks[d][kb + k], acc);
                s[k] = acc;
            }
            float tm = s[0];
            #pragma unroll
            for (int k = 1; k < 32; k++) tm = fmaxf(tm, s[k]);
            const float nm   = fmaxf(m, tm);
            const float corr = __expf(m - nm);
            l *= corr;
            #pragma unroll
            for (int d = 0; d < HDIM; d++) o[d] *= corr;
            #pragma unroll
            for (int k = 0; k < 32; k++) {
                const float p = __expf(s[k] - nm);
                l += p;
                #pragma unroll
                for (int d = 0; d < HDIM; d++)
                    o[d] = fmaf(p, Vs[d][kb + k], o[d]);
            }
            m = nm;
        }
    }

    const float inv = 1.f / l;
    float* op = g_attn + (size_t)(b * SEQ + qrow) * DIM + h * HDIM;
    #pragma unroll
    for (int i = 0; i < 8; i++)
        ((float4*)op)[i] = make_float4(o[4*i+0]*inv, o[4*i+1]*inv,
                                       o[4*i+2]*inv, o[4*i+3]*inv);
}

// ---------------- residual add + LayerNorm (in place into g_h) --------------
__global__ void __launch_bounds__(256) add_ln_k(
    const float* __restrict__ gamma, const float* __restrict__ beta)
{
    const int warp = threadIdx.x >> 5;
    const int lane = threadIdx.x & 31;
    const int row  = blockIdx.x * 8 + warp;

    const float* r  = g_h   + (size_t)row * DIM;
    const float* dl = g_tmp + (size_t)row * DIM;

    float v[4];
    #pragma unroll
    for (int i = 0; i < 4; i++) v[i] = r[lane + 32*i] + dl[lane + 32*i];

    float s = v[0] + v[1] + v[2] + v[3];
    #pragma unroll
    for (int off = 16; off; off >>= 1) s += __shfl_xor_sync(~0u, s, off);
    const float mean = s * (1.f / DIM);

    float var = 0.f;
    #pragma unroll
    for (int i = 0; i < 4; i++) { float d = v[i] - mean; var = fmaf(d, d, var); }
    #pragma unroll
    for (int off = 16; off; off >>= 1) var += __shfl_xor_sync(~0u, var, off);
    const float inv = rsqrtf(var * (1.f / DIM) + 1e-5f);

    float* w = g_h + (size_t)row * DIM;
    #pragma unroll
    for (int i = 0; i < 4; i++) {
        const int c = lane + 32*i;
        w[c] = (v[i] - mean) * inv * gamma[c] + beta[c];
    }
}

// ---------------- node mask from post-projection h ---------------------------
__global__ void __launch_bounds__(256) mask_k()
{
    const int warp = threadIdx.x >> 5;
    const int lane = threadIdx.x & 31;
    const int row  = blockIdx.x * 8 + warp;
    const float* r = g_h + (size_t)row * DIM;
    float s = 0.f;
    #pragma unroll
    for (int i = 0; i < 4; i++) s += r[lane + 32*i];
    #pragma unroll
    for (int off = 16; off; off >>= 1) s += __shfl_xor_sync(~0u, s, off);
    if (lane == 0) g_mask[row] = (s != 0.f) ? 1.f : 0.f;
}

// ---------------- masked mean pooling ---------------------------------------
__global__ void __launch_bounds__(DIM) pool_k(float* __restrict__ out)
{
    const int b = blockIdx.x;
    const int d = threadIdx.x;
    float acc = 0.f, ms = 0.f;
    for (int s = 0; s < SEQ; s++) {
        const float mk = g_mask[b * SEQ + s];
        acc = fmaf(g_h[(size_t)(b * SEQ + s) * DIM + d], mk, acc);
        ms += mk;
    }
    out[b * DIM + d] = acc / ms;
}

// ---------------- driver -----------------------------------------------------
extern "C" void kernel_launch(void* const* d_in, const int* in_sizes, int n_in,
                              void* d_out, int out_size)
{
    const float* x     = (const float*)d_in[0];   // [N, 64]
    const float* W_in  = (const float*)d_in[2];   // [128, 64]
    const float* b_in  = (const float*)d_in[3];   // [128]
    const float* Wqkv  = (const float*)d_in[4];   // [L, 384, 128]
    const float* bqkv  = (const float*)d_in[5];   // [L, 384]
    const float* Wo    = (const float*)d_in[6];   // [L, 128, 128]
    const float* bo    = (const float*)d_in[7];   // [L, 128]
    const float* W1    = (const float*)d_in[8];   // [L, 2048, 128]
    const float* b1    = (const float*)d_in[9];   // [L, 2048]
    const float* W2    = (const float*)d_in[10];  // [L, 128, 2048]
    const float* b2    = (const float*)d_in[11];  // [L, 128]
    const float* ln1g  = (const float*)d_in[12];
    const float* ln1b  = (const float*)d_in[13];
    const float* ln2g  = (const float*)d_in[14];
    const float* ln2b  = (const float*)d_in[15];
    float* out = (float*)d_out;

    static bool attr_done = false;
    if (!attr_done) {
        cudaFuncSetAttribute(gemm_mma_k<false>,
            cudaFuncAttributeMaxDynamicSharedMemorySize, SMEM_DYN);
        cudaFuncSetAttribute(gemm_mma_k<true>,
            cudaFuncAttributeMaxDynamicSharedMemorySize, SMEM_DYN);
        attr_done = true;
    }

    const int MROW = NTOT / 128;   // 256 row-tiles

    gemm_mma_k<false><<<dim3(1, MROW), 256, SMEM_DYN>>>(5, x, W_in, b_in, 0, DIM, INDIM);
    mask_k<<<NTOT/8, 256>>>();

    for (int l = 0; l < NLAY; l++) {
        gemm_mma_k<false><<<dim3(3, MROW), 256, SMEM_DYN>>>(
            0, nullptr, Wqkv + (size_t)l*3*DIM*DIM, bqkv + l*3*DIM, 1, 3*DIM, DIM);
        attn_k<<<NB*NHEAD*(SEQ/128), 128>>>();
        gemm_mma_k<false><<<dim3(1, MROW), 256, SMEM_DYN>>>(
            2, nullptr, Wo + (size_t)l*DIM*DIM, bo + l*DIM, 3, DIM, DIM);
        add_ln_k<<<NTOT/8, 256>>>(ln1g + l*DIM, ln1b + l*DIM);
        gemm_mma_k<true><<<dim3(DFF/128, MROW), 256, SMEM_DYN>>>(
            0, nullptr, W1 + (size_t)l*DFF*DIM, b1 + l*DFF, 4, DFF, DIM);
        gemm_mma_k<false><<<dim3(1, MROW), 256, SMEM_DYN>>>(
            4, nullptr, W2 + (size_t)l*DIM*DFF, b2 + l*DIM, 3, DIM, DFF);
        add_ln_k<<<NTOT/8, 256>>>(ln2g + l*DIM, ln2b + l*DIM);
    }

    pool_k<<<NB, DIM>>>(out);
}